// round 6
// baseline (speedup 1.0000x reference)
#include <cuda_runtime.h>
#include <cuda_fp16.h>
#include <cstdint>

#define BB 2
#define TT 512
#define CC 128
#define C2 256
#define HS 64

// ---------------- scratch (no allocations allowed) -------------------------
__device__ float g_K[BB*TT*CC];
__device__ float g_Q[BB*TT*CC];
__device__ float g_V[BB*TT*HS];
__device__ float g_S[(size_t)BB*TT*TT];
// W1^T (n-major) fp16, swizzled: 4 K-chunks x 16KB
__device__ __align__(16) unsigned char g_Bimg[4*16384];

__device__ __forceinline__ uint32_t smem_u32(const void* p) {
    uint32_t a;
    asm("{ .reg .u64 t; cvta.to.shared.u64 t, %1; cvt.u32.u64 %0, t; }" : "=r"(a) : "l"(p));
    return a;
}
// row-local swizzle: rows are 128B; XOR 16B-bank by (row&7)
#define SWZB(row, kbyte) ((uint32_t)(row)*128u + (((uint32_t)(kbyte)) ^ ((((uint32_t)(row))&7u)*16u)))

__device__ __forceinline__ void ldsm_x4(uint32_t addr, uint32_t& r0, uint32_t& r1,
                                        uint32_t& r2, uint32_t& r3) {
    asm volatile("ldmatrix.sync.aligned.m8n8.x4.shared.b16 {%0,%1,%2,%3}, [%4];"
                 : "=r"(r0), "=r"(r1), "=r"(r2), "=r"(r3) : "r"(addr));
}
__device__ __forceinline__ void mma16816(float* d, const uint32_t* a, uint32_t b0, uint32_t b1) {
    asm volatile("mma.sync.aligned.m16n8k16.row.col.f32.f16.f16.f32 "
                 "{%0,%1,%2,%3}, {%4,%5,%6,%7}, {%8,%9}, {%0,%1,%2,%3};"
                 : "+f"(d[0]), "+f"(d[1]), "+f"(d[2]), "+f"(d[3])
                 : "r"(a[0]), "r"(a[1]), "r"(a[2]), "r"(a[3]), "r"(b0), "r"(b1));
}
__device__ __forceinline__ uint32_t pack_h2(float2 v) {
    __half2 h = __floats2half2_rn(v.x, v.y);
    return *(uint32_t*)&h;
}

// ---------------------------------------------------------------------------
// Kernel 0: W1 -> W1^T fp16 swizzled image (4 chunks of K=64)
// ---------------------------------------------------------------------------
__global__ void prepB_kernel(const float* __restrict__ W1) {
    int t = blockIdx.x * 256 + threadIdx.x;   // 0 .. 32767
    if (t >= 4*128*64) return;
    int c   = t >> 13;
    int rem = t & 8191;
    int n   = rem >> 6;
    int kk  = rem & 63;
    float w = W1[(c*64 + kk) * CC + n];
    *(__half*)(g_Bimg + c*16384 + SWZB(n, kk*2)) = __float2half_rn(w);
}

// ---------------------------------------------------------------------------
// Kernel 1: K/Q/V.  4 rows per block, 256 threads, 256 blocks (2 waves).
// ---------------------------------------------------------------------------
__global__ void kqv_kernel(const float* __restrict__ x,
                           const float* __restrict__ W1,
                           const float* __restrict__ Wv,
                           const float* __restrict__ bv) {
    __shared__ float sx[4][CC];
    int r0 = blockIdx.x * 4;
    int t = threadIdx.x;
    for (int idx = t; idx < 4*CC; idx += 256)
        sx[idx >> 7][idx & 127] = x[(r0 + (idx >> 7))*CC + (idx & 127)];
    __syncthreads();

    int h = t & 127;
    const float* Wcol = (t < 128) ? W1 : (W1 + CC*CC);
    float a[4] = {0.f, 0.f, 0.f, 0.f};
#pragma unroll 8
    for (int d = 0; d < CC; d++) {
        float w = Wcol[d*CC + h];
#pragma unroll
        for (int r = 0; r < 4; r++) a[r] = fmaf(sx[r][d], w, a[r]);
    }
    float* dst = (t < 128) ? g_K : g_Q;
#pragma unroll
    for (int r = 0; r < 4; r++) dst[(r0 + r)*CC + h] = a[r];

    if (t < HS) {
        float v[4];
        float bvh = bv[t];
#pragma unroll
        for (int r = 0; r < 4; r++) v[r] = bvh;
#pragma unroll 8
        for (int d = 0; d < CC; d++) {
            float w = Wv[d*HS + t];
#pragma unroll
            for (int r = 0; r < 4; r++) v[r] = fmaf(sx[r][d], w, v[r]);
        }
#pragma unroll
        for (int r = 0; r < 4; r++) g_V[(r0 + r)*HS + t] = v[r];
    }
}

// ---------------------------------------------------------------------------
// Kernel 2: fp16 HMMA P-GEMM, A direct-from-gmem in fragment layout
//   block = (i, 128-j tile), 256 threads = 8 warps (4 j x 2 n), warp 32x64
//   smem: [0,64K) B image, [64K..) misc.  NO syncs in main loop.
// ---------------------------------------------------------------------------
#define MISC  65536
#define SMEM_BYTES (MISC + 4096)

__global__ void __launch_bounds__(256, 2)
score_kernel(const float* __restrict__ pd,
             const float* __restrict__ b1,
             const float* __restrict__ W2,
             const float* __restrict__ b2) {
    int i = blockIdx.x;
    int jbase = blockIdx.y * 128;
    if (jbase > i) return;

    extern __shared__ __align__(16) unsigned char sm[];
    uint32_t base = smem_u32(sm);

    int tid  = threadIdx.x;
    int lane = tid & 31;
    int wid  = tid >> 5;
    int warp_j = wid & 3;    // 4 x 32 rows
    int warp_n = wid >> 2;   // 2 x 64 cols

    float* w2s   = (float*)(sm + MISC);          // 128 f
    float* qs    = (float*)(sm + MISC + 512);    // 2x128 f
    float* partS = (float*)(sm + MISC + 1536);   // 512 f
    float* b2s   = (float*)(sm + MISC + 3584);

    if (tid < 128) w2s[tid] = W2[tid];
    if (tid == 0)  b2s[0] = b2[0];
    {
        int b = tid >> 7, h = tid & 127;
        qs[b*128 + h] = g_Q[((size_t)(b*TT + i))*CC + h] + b1[h];
    }
    {   // B image -> smem (64KB)
        const float4* src = (const float4*)g_Bimg;
        float4* dst = (float4*)sm;
        for (int idx = tid; idx < 4096; idx += 256) dst[idx] = src[idx];
    }
    __syncthreads();

    float acc[2][8][4];
#pragma unroll
    for (int jt = 0; jt < 2; jt++)
#pragma unroll
        for (int nt = 0; nt < 8; nt++)
#pragma unroll
            for (int r = 0; r < 4; r++) acc[jt][nt][r] = 0.f;

    // A row base pointers in fragment layout: [jt][rowpair(+0/+8)]
    const float* aptr[2][2];
#pragma unroll
    for (int jt = 0; jt < 2; jt++)
#pragma unroll
        for (int rp = 0; rp < 2; rp++) {
            int j = warp_j*32 + jt*16 + (lane >> 2) + rp*8;
            aptr[jt][rp] = pd + ((size_t)i*TT + jbase + j)*C2 + (lane & 3)*2;
        }

    float2 pre[2][4];   // [jt][a0..a3 source]
#define LDA(kk)                                                            \
    do {                                                                   \
        _Pragma("unroll")                                                  \
        for (int jt = 0; jt < 2; jt++) {                                   \
            pre[jt][0] = *(const float2*)(aptr[jt][0] + (kk)*16);          \
            pre[jt][1] = *(const float2*)(aptr[jt][1] + (kk)*16);          \
            pre[jt][2] = *(const float2*)(aptr[jt][0] + (kk)*16 + 8);      \
            pre[jt][3] = *(const float2*)(aptr[jt][1] + (kk)*16 + 8);      \
        }                                                                  \
    } while (0)

    LDA(0);

    // B fragment address pieces (constant across kk except chunk/kkin)
    int bn = warp_n*64 + (lane & 7) + ((lane >> 4) << 3);
    uint32_t bk_half = ((lane >> 3) & 1) * 16u;   // byte offset of +8 k within step

#pragma unroll
    for (int kk = 0; kk < 16; kk++) {
        // convert current A prefetch to fragments
        uint32_t a[2][4];
#pragma unroll
        for (int jt = 0; jt < 2; jt++)
#pragma unroll
            for (int q = 0; q < 4; q++) a[jt][q] = pack_h2(pre[jt][q]);

        // prefetch next kk
        if (kk < 15) LDA(kk + 1);

        int c    = kk >> 2;
        int kkin = kk & 3;
        uint32_t bBase = base + (uint32_t)c*16384u;
        uint32_t kb = (uint32_t)kkin*32u + bk_half;

#pragma unroll
        for (int p = 0; p < 4; p++) {
            int n = bn + p*16;
            uint32_t b0, b1r, b2r, b3;
            ldsm_x4(bBase + SWZB(n, kb), b0, b1r, b2r, b3);
            mma16816(acc[0][2*p],   a[0], b0,  b1r);
            mma16816(acc[0][2*p+1], a[0], b2r, b3);
            mma16816(acc[1][2*p],   a[1], b0,  b1r);
            mma16816(acc[1][2*p+1], a[1], b2r, b3);
        }
    }

    // --- epilogue: gelu + W2 dot in fragment layout; K from L2-hot gmem
#pragma unroll
    for (int b = 0; b < BB; b++) {
        const float* qb = qs + b*128;
#pragma unroll
        for (int jt = 0; jt < 2; jt++)
#pragma unroll
            for (int rh = 0; rh < 2; rh++) {
                int j = warp_j*32 + jt*16 + (lane >> 2) + 8*rh;
                const float* kb = g_K + ((size_t)(b*TT + jbase + j))*CC;
                float partial = 0.f;
#pragma unroll
                for (int nt = 0; nt < 8; nt++) {
                    int h0 = warp_n*64 + nt*8 + (lane & 3)*2;
                    float2 kv = *(const float2*)(kb + h0);
                    float pre0 = acc[jt][nt][rh*2 + 0] + qb[h0]     + kv.x;
                    float pre1 = acc[jt][nt][rh*2 + 1] + qb[h0 + 1] + kv.y;
                    partial = fmaf(pre0 * normcdff(pre0), w2s[h0],     partial);
                    partial = fmaf(pre1 * normcdff(pre1), w2s[h0 + 1], partial);
                }
                partial += __shfl_xor_sync(0xffffffffu, partial, 1);
                partial += __shfl_xor_sync(0xffffffffu, partial, 2);
                if ((lane & 3) == 0)
                    partS[warp_n*256 + b*128 + j] = partial;
            }
    }
    __syncthreads();

    {
        int b = tid >> 7, j = tid & 127;
        int jg = jbase + j;
        if (jg <= i)
            g_S[((size_t)(b*TT + i))*TT + jg] =
                partS[b*128 + j] + partS[256 + b*128 + j] + b2s[0];
    }
}

// ---------------------------------------------------------------------------
// Kernel 3: causal softmax (scaled) + wei @ V, 256 threads
// ---------------------------------------------------------------------------
__global__ void softmax_av_kernel(float* __restrict__ out) {
    int bi = blockIdx.x;
    int b = bi >> 9, i = bi & 511;
    int t = threadIdx.x;
    int n = i + 1;

    __shared__ float p[TT];
    __shared__ float red[256];
    const float scale = 0.088388347648318447f;
    const float* srow = &g_S[((size_t)(b*TT + i))*TT];

    float m = -1e30f;
    for (int j = t; j < n; j += 256) m = fmaxf(m, srow[j]*scale);
    red[t] = m; __syncthreads();
    for (int s = 128; s; s >>= 1) { if (t < s) red[t] = fmaxf(red[t], red[t+s]); __syncthreads(); }
    m = red[0]; __syncthreads();

    float sum = 0.f;
    for (int j = t; j < n; j += 256) {
        float e = expf(srow[j]*scale - m);
        p[j] = e;
        sum += e;
    }
    red[t] = sum; __syncthreads();
    for (int s = 128; s; s >>= 1) { if (t < s) red[t] += red[t+s]; __syncthreads(); }
    float inv = 1.f / red[0];
    __syncthreads();

    // AV: 4 j-slices in parallel, h = t&63
    int h = t & 63, slice = t >> 6;
    float acc = 0.f;
    for (int j = slice; j < n; j += 4)
        acc = fmaf(p[j], g_V[((size_t)(b*TT + j))*HS + h], acc);
    red[t] = acc; __syncthreads();
    if (t < HS)
        out[((size_t)(b*TT + i))*HS + t] =
            (red[t] + red[t+64] + red[t+128] + red[t+192]) * inv;
}

// ---------------------------------------------------------------------------
extern "C" void kernel_launch(void* const* d_in, const int* in_sizes, int n_in,
                              void* d_out, int out_size) {
    const float* x  = (const float*)d_in[0];
    const float* pd = (const float*)d_in[2];
    const float* W1 = (const float*)d_in[3];
    const float* b1 = (const float*)d_in[4];
    const float* W2 = (const float*)d_in[5];
    const float* b2 = (const float*)d_in[6];
    const float* Wv = (const float*)d_in[7];
    const float* bv = (const float*)d_in[8];
    float* out = (float*)d_out;

    cudaFuncSetAttribute(score_kernel, cudaFuncAttributeMaxDynamicSharedMemorySize, SMEM_BYTES);

    prepB_kernel<<<128, 256>>>(W1);
    kqv_kernel<<<256, 256>>>(x, W1, Wv, bv);
    score_kernel<<<dim3(TT, 4), 256, SMEM_BYTES>>>(pd, b1, W2, b2);
    softmax_av_kernel<<<BB*TT, 256>>>(out);
}

// round 7
// speedup vs baseline: 1.5492x; 1.5492x over previous
#include <cuda_runtime.h>
#include <cuda_fp16.h>
#include <cstdint>

#define BB 2
#define TT 512
#define CC 128
#define C2 256
#define HS 64

// ---------------- scratch (no allocations allowed) -------------------------
__device__ float g_K[BB*TT*CC];
__device__ float g_Q[BB*TT*CC];
__device__ float g_V[BB*TT*HS];
__device__ float g_S[(size_t)BB*TT*TT];
// W1^T (n-major) fp16, swizzled: 4 K-chunks x 16KB
__device__ __align__(16) unsigned char g_Bimg[4*16384];

__device__ __forceinline__ uint32_t smem_u32(const void* p) {
    uint32_t a;
    asm("{ .reg .u64 t; cvta.to.shared.u64 t, %1; cvt.u32.u64 %0, t; }" : "=r"(a) : "l"(p));
    return a;
}
// row-local swizzle: rows are 128B; XOR 16B-bank by (row&7)
#define SWZB(row, kbyte) ((uint32_t)(row)*128u + (((uint32_t)(kbyte)) ^ ((((uint32_t)(row))&7u)*16u)))

__device__ __forceinline__ void ldsm_x4(uint32_t addr, uint32_t& r0, uint32_t& r1,
                                        uint32_t& r2, uint32_t& r3) {
    asm volatile("ldmatrix.sync.aligned.m8n8.x4.shared.b16 {%0,%1,%2,%3}, [%4];"
                 : "=r"(r0), "=r"(r1), "=r"(r2), "=r"(r3) : "r"(addr));
}
__device__ __forceinline__ void mma16816(float* d, const uint32_t* a, uint32_t b0, uint32_t b1) {
    asm volatile("mma.sync.aligned.m16n8k16.row.col.f32.f16.f16.f32 "
                 "{%0,%1,%2,%3}, {%4,%5,%6,%7}, {%8,%9}, {%0,%1,%2,%3};"
                 : "+f"(d[0]), "+f"(d[1]), "+f"(d[2]), "+f"(d[3])
                 : "r"(a[0]), "r"(a[1]), "r"(a[2]), "r"(a[3]), "r"(b0), "r"(b1));
}
// exact gelu via erff (cheap polynomial, no exp path)
__device__ __forceinline__ float gelu_exact(float x) {
    return 0.5f * x * (1.f + erff(x * 0.70710678118654752f));
}

// ---------------------------------------------------------------------------
// Kernel 0: W1 -> W1^T fp16 swizzled image (4 chunks of K=64)
// ---------------------------------------------------------------------------
__global__ void prepB_kernel(const float* __restrict__ W1) {
    int t = blockIdx.x * 256 + threadIdx.x;   // 0 .. 32767
    if (t >= 4*128*64) return;
    int c   = t >> 13;
    int rem = t & 8191;
    int n   = rem >> 6;
    int kk  = rem & 63;
    float w = W1[(c*64 + kk) * CC + n];
    *(__half*)(g_Bimg + c*16384 + SWZB(n, kk*2)) = __float2half_rn(w);
}

// ---------------------------------------------------------------------------
// Kernel 1: K/Q/V.  4 rows per block, 256 threads, 256 blocks (2 waves).
// ---------------------------------------------------------------------------
__global__ void kqv_kernel(const float* __restrict__ x,
                           const float* __restrict__ W1,
                           const float* __restrict__ Wv,
                           const float* __restrict__ bv) {
    __shared__ float sx[4][CC];
    int r0 = blockIdx.x * 4;
    int t = threadIdx.x;
    for (int idx = t; idx < 4*CC; idx += 256)
        sx[idx >> 7][idx & 127] = x[(r0 + (idx >> 7))*CC + (idx & 127)];
    __syncthreads();

    int h = t & 127;
    const float* Wcol = (t < 128) ? W1 : (W1 + CC*CC);
    float a[4] = {0.f, 0.f, 0.f, 0.f};
#pragma unroll 8
    for (int d = 0; d < CC; d++) {
        float w = Wcol[d*CC + h];
#pragma unroll
        for (int r = 0; r < 4; r++) a[r] = fmaf(sx[r][d], w, a[r]);
    }
    float* dst = (t < 128) ? g_K : g_Q;
#pragma unroll
    for (int r = 0; r < 4; r++) dst[(r0 + r)*CC + h] = a[r];

    if (t < HS) {
        float v[4];
        float bvh = bv[t];
#pragma unroll
        for (int r = 0; r < 4; r++) v[r] = bvh;
#pragma unroll 8
        for (int d = 0; d < CC; d++) {
            float w = Wv[d*HS + t];
#pragma unroll
            for (int r = 0; r < 4; r++) v[r] = fmaf(sx[r][d], w, v[r]);
        }
#pragma unroll
        for (int r = 0; r < 4; r++) g_V[(r0 + r)*HS + t] = v[r];
    }
}

// ---------------------------------------------------------------------------
// Kernel 2: fp16 HMMA P-GEMM (smem-staged A, double-buffered) + erff epilogue
//   block = (i, 128-j tile), 256 threads = 8 warps (4 j x 2 n), warp 32x64
// smem: [0,64K) B image  [64K,80K) A buf0  [80K,96K) A buf1  [96K..) misc
// ---------------------------------------------------------------------------
#define A0_OFF 65536
#define A1_OFF 81920
#define MISC   98304
#define SMEM_BYTES (MISC + 4096)

__global__ void __launch_bounds__(256, 2)
score_kernel(const float* __restrict__ pd,
             const float* __restrict__ b1,
             const float* __restrict__ W2,
             const float* __restrict__ b2) {
    int i = blockIdx.x;
    int jbase = blockIdx.y * 128;
    if (jbase > i) return;

    extern __shared__ __align__(16) unsigned char sm[];
    uint32_t base = smem_u32(sm);

    int tid  = threadIdx.x;
    int lane = tid & 31;
    int wid  = tid >> 5;
    int warp_j = wid & 3;    // 4 x 32 rows
    int warp_n = wid >> 2;   // 2 x 64 cols

    float* w2s   = (float*)(sm + MISC);          // 128 f
    float* qs    = (float*)(sm + MISC + 512);    // 2x128 f
    float* partS = (float*)(sm + MISC + 1536);   // 512 f
    float* b2s   = (float*)(sm + MISC + 3584);

    if (tid < 128) w2s[tid] = W2[tid];
    if (tid == 0)  b2s[0] = b2[0];
    {
        int b = tid >> 7, h = tid & 127;
        qs[b*128 + h] = g_Q[((size_t)(b*TT + i))*CC + h] + b1[h];
    }
    {   // B image -> smem (64KB)
        const float4* src = (const float4*)g_Bimg;
        float4* dst = (float4*)sm;
        for (int idx = tid; idx < 4096; idx += 256) dst[idx] = src[idx];
    }

    const float4* prow = (const float4*)(pd + ((size_t)i*TT + jbase)*C2);

    // per-thread fixed conversion coordinates
    int cv_j  = tid >> 1;            // with it-loop: idx = tid + it*256
    (void)cv_j;

#define CONVERT_CHUNK(c, abuf)                                                  \
    do {                                                                        \
        _Pragma("unroll")                                                       \
        for (int it = 0; it < 8; it++) {                                        \
            int idx = tid + it*256;          /* 0..2047 */                      \
            int j   = idx >> 4;                                                 \
            int f4  = idx & 15;                                                 \
            float4 v = prow[j*64 + (c)*16 + f4];                                \
            __half2 p0 = __floats2half2_rn(v.x, v.y);                           \
            __half2 p1 = __floats2half2_rn(v.z, v.w);                           \
            unsigned long long h64 =                                            \
                  (unsigned long long)(*(uint32_t*)&p0)                         \
                | ((unsigned long long)(*(uint32_t*)&p1) << 32);                \
            *(unsigned long long*)(sm + (abuf) + SWZB(j, f4*8)) = h64;          \
        }                                                                       \
    } while (0)

    float acc[2][8][4];
#pragma unroll
    for (int jt = 0; jt < 2; jt++)
#pragma unroll
        for (int nt = 0; nt < 8; nt++)
#pragma unroll
            for (int r = 0; r < 4; r++) acc[jt][nt][r] = 0.f;

    // prologue: chunk 0 into buf0
    CONVERT_CHUNK(0, A0_OFF);
    __syncthreads();

#pragma unroll
    for (int c = 0; c < 4; c++) {
        uint32_t aCur = (c & 1) ? A1_OFF : A0_OFF;
        // convert next chunk into the other buffer (overlaps MMA below)
        if (c < 3) {
            uint32_t aNext = (c & 1) ? A0_OFF : A1_OFF;
            CONVERT_CHUNK(c + 1, aNext);
        }

        uint32_t bBase = base + (uint32_t)c*16384u;
#pragma unroll
        for (int kk = 0; kk < 4; kk++) {
            int k0 = kk*16;
            uint32_t a0[4], a1[4];
            {
                uint32_t kb = (uint32_t)(k0 + ((lane >> 4) & 1)*8)*2u;
                int j0 = warp_j*32 + (lane & 15);
                ldsm_x4(base + aCur + SWZB(j0, kb), a0[0], a0[1], a0[2], a0[3]);
                int j1 = j0 + 16;
                ldsm_x4(base + aCur + SWZB(j1, kb), a1[0], a1[1], a1[2], a1[3]);
            }
#pragma unroll
            for (int p = 0; p < 4; p++) {
                int n = warp_n*64 + p*16 + (lane & 7) + ((lane >> 4) << 3);
                uint32_t kb = (uint32_t)(k0 + ((lane >> 3) & 1)*8)*2u;
                uint32_t b0, b1r, b2r, b3;
                ldsm_x4(bBase + SWZB(n, kb), b0, b1r, b2r, b3);
                mma16816(acc[0][2*p],   a0, b0,  b1r);
                mma16816(acc[0][2*p+1], a0, b2r, b3);
                mma16816(acc[1][2*p],   a1, b0,  b1r);
                mma16816(acc[1][2*p+1], a1, b2r, b3);
            }
        }
        __syncthreads();   // next-buffer writes visible; current buffer free
    }

    // --- epilogue: erff gelu + W2 dot in fragment layout; K from L2-hot gmem
#pragma unroll
    for (int b = 0; b < BB; b++) {
        const float* qb = qs + b*128;
#pragma unroll
        for (int jt = 0; jt < 2; jt++)
#pragma unroll
            for (int rh = 0; rh < 2; rh++) {
                int j = warp_j*32 + jt*16 + (lane >> 2) + 8*rh;
                const float* kb = g_K + ((size_t)(b*TT + jbase + j))*CC;
                float partial = 0.f;
#pragma unroll
                for (int nt = 0; nt < 8; nt++) {
                    int h0 = warp_n*64 + nt*8 + (lane & 3)*2;
                    float2 kv = *(const float2*)(kb + h0);
                    float pre0 = acc[jt][nt][rh*2 + 0] + qb[h0]     + kv.x;
                    float pre1 = acc[jt][nt][rh*2 + 1] + qb[h0 + 1] + kv.y;
                    partial = fmaf(gelu_exact(pre0), w2s[h0],     partial);
                    partial = fmaf(gelu_exact(pre1), w2s[h0 + 1], partial);
                }
                partial += __shfl_xor_sync(0xffffffffu, partial, 1);
                partial += __shfl_xor_sync(0xffffffffu, partial, 2);
                if ((lane & 3) == 0)
                    partS[warp_n*256 + b*128 + j] = partial;
            }
    }
    __syncthreads();

    {
        int b = tid >> 7, j = tid & 127;
        int jg = jbase + j;
        if (jg <= i)
            g_S[((size_t)(b*TT + i))*TT + jg] =
                partS[b*128 + j] + partS[256 + b*128 + j] + b2s[0];
    }
}

// ---------------------------------------------------------------------------
// Kernel 3: causal softmax (scaled) + wei @ V, 256 threads
// ---------------------------------------------------------------------------
__global__ void softmax_av_kernel(float* __restrict__ out) {
    int bi = blockIdx.x;
    int b = bi >> 9, i = bi & 511;
    int t = threadIdx.x;
    int n = i + 1;

    __shared__ float p[TT];
    __shared__ float red[256];
    const float scale = 0.088388347648318447f;
    const float* srow = &g_S[((size_t)(b*TT + i))*TT];

    float m = -1e30f;
    for (int j = t; j < n; j += 256) m = fmaxf(m, srow[j]*scale);
    red[t] = m; __syncthreads();
    for (int s = 128; s; s >>= 1) { if (t < s) red[t] = fmaxf(red[t], red[t+s]); __syncthreads(); }
    m = red[0]; __syncthreads();

    float sum = 0.f;
    for (int j = t; j < n; j += 256) {
        float e = expf(srow[j]*scale - m);
        p[j] = e;
        sum += e;
    }
    red[t] = sum; __syncthreads();
    for (int s = 128; s; s >>= 1) { if (t < s) red[t] += red[t+s]; __syncthreads(); }
    float inv = 1.f / red[0];
    __syncthreads();

    int h = t & 63, slice = t >> 6;
    float acc = 0.f;
    for (int j = slice; j < n; j += 4)
        acc = fmaf(p[j], g_V[((size_t)(b*TT + j))*HS + h], acc);
    red[t] = acc; __syncthreads();
    if (t < HS)
        out[((size_t)(b*TT + i))*HS + t] =
            (red[t] + red[t+64] + red[t+128] + red[t+192]) * inv;
}

// ---------------------------------------------------------------------------
extern "C" void kernel_launch(void* const* d_in, const int* in_sizes, int n_in,
                              void* d_out, int out_size) {
    const float* x  = (const float*)d_in[0];
    const float* pd = (const float*)d_in[2];
    const float* W1 = (const float*)d_in[3];
    const float* b1 = (const float*)d_in[4];
    const float* W2 = (const float*)d_in[5];
    const float* b2 = (const float*)d_in[6];
    const float* Wv = (const float*)d_in[7];
    const float* bv = (const float*)d_in[8];
    float* out = (float*)d_out;

    cudaFuncSetAttribute(score_kernel, cudaFuncAttributeMaxDynamicSharedMemorySize, SMEM_BYTES);

    prepB_kernel<<<128, 256>>>(W1);
    kqv_kernel<<<256, 256>>>(x, W1, Wv, bv);
    score_kernel<<<dim3(TT, 4), 256, SMEM_BYTES>>>(pd, b1, W2, b2);
    softmax_av_kernel<<<BB*TT, 256>>>(out);
}

// round 8
// speedup vs baseline: 1.7153x; 1.1072x over previous
#include <cuda_runtime.h>
#include <cuda_fp16.h>
#include <cstdint>

#define BB 2
#define TT 512
#define CC 128
#define C2 256
#define HS 64

// ---------------- scratch (no allocations allowed) -------------------------
__device__ float g_K[BB*TT*CC];
__device__ float g_Q[BB*TT*CC];
__device__ float g_V[BB*TT*HS];
__device__ float g_S[(size_t)BB*TT*TT];
// W1^T (n-major) fp16, swizzled: 4 K-chunks x 16KB
__device__ __align__(16) unsigned char g_Bimg[4*16384];

__device__ __forceinline__ uint32_t smem_u32(const void* p) {
    uint32_t a;
    asm("{ .reg .u64 t; cvta.to.shared.u64 t, %1; cvt.u32.u64 %0, t; }" : "=r"(a) : "l"(p));
    return a;
}
// row-local swizzle: rows are 128B; XOR 16B-bank by (row&7)
#define SWZB(row, kbyte) ((uint32_t)(row)*128u + (((uint32_t)(kbyte)) ^ ((((uint32_t)(row))&7u)*16u)))

__device__ __forceinline__ void ldsm_x4(uint32_t addr, uint32_t& r0, uint32_t& r1,
                                        uint32_t& r2, uint32_t& r3) {
    asm volatile("ldmatrix.sync.aligned.m8n8.x4.shared.b16 {%0,%1,%2,%3}, [%4];"
                 : "=r"(r0), "=r"(r1), "=r"(r2), "=r"(r3) : "r"(addr));
}
// fp16-accumulate HMMA (2 output regs = 4 halves)
__device__ __forceinline__ void mma16816h(uint32_t* d, const uint32_t* a, uint32_t b0, uint32_t b1) {
    asm volatile("mma.sync.aligned.m16n8k16.row.col.f16.f16.f16.f16 "
                 "{%0,%1}, {%2,%3,%4,%5}, {%6,%7}, {%0,%1};"
                 : "+r"(d[0]), "+r"(d[1])
                 : "r"(a[0]), "r"(a[1]), "r"(a[2]), "r"(a[3]), "r"(b0), "r"(b1));
}
// exact gelu via erff (cheap polynomial, no exp path)
__device__ __forceinline__ float gelu_exact(float x) {
    return 0.5f * x * (1.f + erff(x * 0.70710678118654752f));
}

// ---------------------------------------------------------------------------
// Kernel 0: W1 -> W1^T fp16 swizzled image (4 chunks of K=64)
// ---------------------------------------------------------------------------
__global__ void prepB_kernel(const float* __restrict__ W1) {
    int t = blockIdx.x * 256 + threadIdx.x;   // 0 .. 32767
    if (t >= 4*128*64) return;
    int c   = t >> 13;
    int rem = t & 8191;
    int n   = rem >> 6;
    int kk  = rem & 63;
    float w = W1[(c*64 + kk) * CC + n];
    *(__half*)(g_Bimg + c*16384 + SWZB(n, kk*2)) = __float2half_rn(w);
}

// ---------------------------------------------------------------------------
// Kernel 1: K/Q/V.  4 rows per block, 256 threads, 256 blocks (2 waves).
// ---------------------------------------------------------------------------
__global__ void kqv_kernel(const float* __restrict__ x,
                           const float* __restrict__ W1,
                           const float* __restrict__ Wv,
                           const float* __restrict__ bv) {
    __shared__ float sx[4][CC];
    int r0 = blockIdx.x * 4;
    int t = threadIdx.x;
    for (int idx = t; idx < 4*CC; idx += 256)
        sx[idx >> 7][idx & 127] = x[(r0 + (idx >> 7))*CC + (idx & 127)];
    __syncthreads();

    int h = t & 127;
    const float* Wcol = (t < 128) ? W1 : (W1 + CC*CC);
    float a[4] = {0.f, 0.f, 0.f, 0.f};
#pragma unroll 8
    for (int d = 0; d < CC; d++) {
        float w = Wcol[d*CC + h];
#pragma unroll
        for (int r = 0; r < 4; r++) a[r] = fmaf(sx[r][d], w, a[r]);
    }
    float* dst = (t < 128) ? g_K : g_Q;
#pragma unroll
    for (int r = 0; r < 4; r++) dst[(r0 + r)*CC + h] = a[r];

    if (t < HS) {
        float v[4];
        float bvh = bv[t];
#pragma unroll
        for (int r = 0; r < 4; r++) v[r] = bvh;
#pragma unroll 8
        for (int d = 0; d < CC; d++) {
            float w = Wv[d*HS + t];
#pragma unroll
            for (int r = 0; r < 4; r++) v[r] = fmaf(sx[r][d], w, v[r]);
        }
#pragma unroll
        for (int r = 0; r < 4; r++) g_V[(r0 + r)*HS + t] = v[r];
    }
}

// ---------------------------------------------------------------------------
// Kernel 2: fp16 HMMA (fp16 accum) P-GEMM, double-buffered A, causal-masked,
//           erff gelu epilogue.
//   block = (i, 128-j tile), 256 threads = 8 warps (4 j x 2 n), warp 32x64
// smem: [0,64K) B image  [64K,80K) A buf0  [80K,96K) A buf1  [96K..) misc
// ---------------------------------------------------------------------------
#define A0_OFF 65536
#define A1_OFF 81920
#define MISC   98304
#define SMEM_BYTES (MISC + 4096)

__global__ void __launch_bounds__(256, 2)
score_kernel(const float* __restrict__ pd,
             const float* __restrict__ b1,
             const float* __restrict__ W2,
             const float* __restrict__ b2) {
    int i = blockIdx.x;
    int jbase = blockIdx.y * 128;
    if (jbase > i) return;
    int jmax = (i - jbase < 128) ? (i - jbase) : 127;   // intra-block causal bound

    extern __shared__ __align__(16) unsigned char sm[];
    uint32_t base = smem_u32(sm);

    int tid  = threadIdx.x;
    int lane = tid & 31;
    int wid  = tid >> 5;
    int warp_j = wid & 3;    // 4 x 32 rows
    int warp_n = wid >> 2;   // 2 x 64 cols
    bool active = (warp_j * 32 <= jmax);

    float* w2s   = (float*)(sm + MISC);          // 128 f
    float* qs    = (float*)(sm + MISC + 512);    // 2x128 f
    float* partS = (float*)(sm + MISC + 1536);   // 512 f
    float* b2s   = (float*)(sm + MISC + 3584);

    if (tid < 128) w2s[tid] = W2[tid];
    if (tid == 0)  b2s[0] = b2[0];
    {
        int b = tid >> 7, h = tid & 127;
        qs[b*128 + h] = g_Q[((size_t)(b*TT + i))*CC + h] + b1[h];
    }
    {   // B image -> smem (64KB)
        const float4* src = (const float4*)g_Bimg;
        float4* dst = (float4*)sm;
        for (int idx = tid; idx < 4096; idx += 256) dst[idx] = src[idx];
    }

    const float4* prow = (const float4*)(pd + ((size_t)i*TT + jbase)*C2);

#define CONVERT_CHUNK(c, abuf)                                                  \
    do {                                                                        \
        _Pragma("unroll")                                                       \
        for (int it = 0; it < 8; it++) {                                        \
            int idx = tid + it*256;          /* 0..2047 */                      \
            int j   = idx >> 4;                                                 \
            int f4  = idx & 15;                                                 \
            if (j <= jmax) {                                                    \
                float4 v = prow[j*64 + (c)*16 + f4];                            \
                __half2 p0 = __floats2half2_rn(v.x, v.y);                       \
                __half2 p1 = __floats2half2_rn(v.z, v.w);                       \
                unsigned long long h64 =                                        \
                      (unsigned long long)(*(uint32_t*)&p0)                     \
                    | ((unsigned long long)(*(uint32_t*)&p1) << 32);            \
                *(unsigned long long*)(sm + (abuf) + SWZB(j, f4*8)) = h64;      \
            }                                                                   \
        }                                                                       \
    } while (0)

    // fp16 accumulators: [jt][nt][2 regs = 4 halves]
    uint32_t acc16[2][8][2];
#pragma unroll
    for (int jt = 0; jt < 2; jt++)
#pragma unroll
        for (int nt = 0; nt < 8; nt++) { acc16[jt][nt][0] = 0u; acc16[jt][nt][1] = 0u; }

    // prologue: chunk 0 into buf0
    CONVERT_CHUNK(0, A0_OFF);
    __syncthreads();

#pragma unroll
    for (int c = 0; c < 4; c++) {
        uint32_t aCur = (c & 1) ? A1_OFF : A0_OFF;
        if (c < 3) {
            uint32_t aNext = (c & 1) ? A0_OFF : A1_OFF;
            CONVERT_CHUNK(c + 1, aNext);
        }

        if (active) {
            uint32_t bBase = base + (uint32_t)c*16384u;
#pragma unroll
            for (int kk = 0; kk < 4; kk++) {
                int k0 = kk*16;
                uint32_t a0[4], a1[4];
                {
                    uint32_t kb = (uint32_t)(k0 + ((lane >> 4) & 1)*8)*2u;
                    int j0 = warp_j*32 + (lane & 15);
                    ldsm_x4(base + aCur + SWZB(j0, kb), a0[0], a0[1], a0[2], a0[3]);
                    int j1 = j0 + 16;
                    ldsm_x4(base + aCur + SWZB(j1, kb), a1[0], a1[1], a1[2], a1[3]);
                }
#pragma unroll
                for (int p = 0; p < 4; p++) {
                    int n = warp_n*64 + p*16 + (lane & 7) + ((lane >> 4) << 3);
                    uint32_t kb = (uint32_t)(k0 + ((lane >> 3) & 1)*8)*2u;
                    uint32_t b0, b1r, b2r, b3;
                    ldsm_x4(bBase + SWZB(n, kb), b0, b1r, b2r, b3);
                    mma16816h(acc16[0][2*p],   a0, b0,  b1r);
                    mma16816h(acc16[0][2*p+1], a0, b2r, b3);
                    mma16816h(acc16[1][2*p],   a1, b0,  b1r);
                    mma16816h(acc16[1][2*p+1], a1, b2r, b3);
                }
            }
        }
        __syncthreads();   // next-buffer writes visible; current buffer free
    }

    // --- epilogue: promote fp16 acc -> fp32, erff gelu + W2 dot
    if (active) {
#pragma unroll
        for (int b = 0; b < BB; b++) {
            const float* qb = qs + b*128;
#pragma unroll
            for (int jt = 0; jt < 2; jt++)
#pragma unroll
                for (int rh = 0; rh < 2; rh++) {
                    int j = warp_j*32 + jt*16 + (lane >> 2) + 8*rh;
                    const float* kb = g_K + ((size_t)(b*TT + jbase + j))*CC;
                    float partial = 0.f;
#pragma unroll
                    for (int nt = 0; nt < 8; nt++) {
                        int h0 = warp_n*64 + nt*8 + (lane & 3)*2;
                        float2 kv = *(const float2*)(kb + h0);
                        float2 av = __half22float2(*(__half2*)&acc16[jt][nt][rh]);
                        float pre0 = av.x + qb[h0]     + kv.x;
                        float pre1 = av.y + qb[h0 + 1] + kv.y;
                        partial = fmaf(gelu_exact(pre0), w2s[h0],     partial);
                        partial = fmaf(gelu_exact(pre1), w2s[h0 + 1], partial);
                    }
                    partial += __shfl_xor_sync(0xffffffffu, partial, 1);
                    partial += __shfl_xor_sync(0xffffffffu, partial, 2);
                    if ((lane & 3) == 0)
                        partS[warp_n*256 + b*128 + j] = partial;
                }
        }
    }
    __syncthreads();

    {
        int b = tid >> 7, j = tid & 127;
        int jg = jbase + j;
        if (jg <= i)
            g_S[((size_t)(b*TT + i))*TT + jg] =
                partS[b*128 + j] + partS[256 + b*128 + j] + b2s[0];
    }
}

// ---------------------------------------------------------------------------
// Kernel 3: causal softmax (scaled) + wei @ V, 256 threads
// ---------------------------------------------------------------------------
__global__ void softmax_av_kernel(float* __restrict__ out) {
    int bi = blockIdx.x;
    int b = bi >> 9, i = bi & 511;
    int t = threadIdx.x;
    int n = i + 1;

    __shared__ float p[TT];
    __shared__ float red[256];
    const float scale = 0.088388347648318447f;
    const float* srow = &g_S[((size_t)(b*TT + i))*TT];

    float m = -1e30f;
    for (int j = t; j < n; j += 256) m = fmaxf(m, srow[j]*scale);
    red[t] = m; __syncthreads();
    for (int s = 128; s; s >>= 1) { if (t < s) red[t] = fmaxf(red[t], red[t+s]); __syncthreads(); }
    m = red[0]; __syncthreads();

    float sum = 0.f;
    for (int j = t; j < n; j += 256) {
        float e = expf(srow[j]*scale - m);
        p[j] = e;
        sum += e;
    }
    red[t] = sum; __syncthreads();
    for (int s = 128; s; s >>= 1) { if (t < s) red[t] += red[t+s]; __syncthreads(); }
    float inv = 1.f / red[0];
    __syncthreads();

    int h = t & 63, slice = t >> 6;
    float acc = 0.f;
    for (int j = slice; j < n; j += 4)
        acc = fmaf(p[j], g_V[((size_t)(b*TT + j))*HS + h], acc);
    red[t] = acc; __syncthreads();
    if (t < HS)
        out[((size_t)(b*TT + i))*HS + t] =
            (red[t] + red[t+64] + red[t+128] + red[t+192]) * inv;
}

// ---------------------------------------------------------------------------
extern "C" void kernel_launch(void* const* d_in, const int* in_sizes, int n_in,
                              void* d_out, int out_size) {
    const float* x  = (const float*)d_in[0];
    const float* pd = (const float*)d_in[2];
    const float* W1 = (const float*)d_in[3];
    const float* b1 = (const float*)d_in[4];
    const float* W2 = (const float*)d_in[5];
    const float* b2 = (const float*)d_in[6];
    const float* Wv = (const float*)d_in[7];
    const float* bv = (const float*)d_in[8];
    float* out = (float*)d_out;

    cudaFuncSetAttribute(score_kernel, cudaFuncAttributeMaxDynamicSharedMemorySize, SMEM_BYTES);

    prepB_kernel<<<128, 256>>>(W1);
    kqv_kernel<<<256, 256>>>(x, W1, Wv, bv);
    score_kernel<<<dim3(TT, 4), 256, SMEM_BYTES>>>(pd, b1, W2, b2);
    softmax_av_kernel<<<BB*TT, 256>>>(out);
}